// round 1
// baseline (speedup 1.0000x reference)
#include <cuda_runtime.h>
#include <math.h>

// ---------------- problem constants ----------------
#define D      2560
#define SSELF  2048
#define SCROSS 512
#define NB     2
#define NH     20
#define HDIM   128
#define FFND   10240
#define TOK    4096     // NB*SSELF
#define TOKC   1024     // NB*SCROSS
#define BH     40       // NB*NH
#define EPSV   1e-6f

// ---------------- scratch (device globals; allocation-free rule) ----------------
__device__ float g_x   [(size_t)TOK * D];
__device__ float g_qkv [(size_t)TOK * 3 * D];
__device__ float g_q   [(size_t)TOK * D];
__device__ float g_k   [(size_t)TOK * D];
__device__ float g_vT  [(size_t)TOK * D];
__device__ float g_attn[(size_t)TOK * D];
__device__ float g_h1  [(size_t)TOK * D];
__device__ float g_h2  [(size_t)TOK * D];
__device__ float g_kv2 [(size_t)TOKC * 2 * D];
__device__ float g_mid [(size_t)TOK * FFND];
__device__ float g_logits[(size_t)BH * SSELF * SSELF];

// ---------------- reductions ----------------
__device__ __forceinline__ float blockReduceSum(float v) {
    __shared__ float sh[32];
    int lane = threadIdx.x & 31, wid = threadIdx.x >> 5;
    #pragma unroll
    for (int o = 16; o > 0; o >>= 1) v += __shfl_xor_sync(0xffffffffu, v, o);
    __syncthreads();
    if (lane == 0) sh[wid] = v;
    __syncthreads();
    int nw = blockDim.x >> 5;
    float r = (threadIdx.x < nw) ? sh[threadIdx.x] : 0.0f;
    if (wid == 0) {
        #pragma unroll
        for (int o = 16; o > 0; o >>= 1) r += __shfl_xor_sync(0xffffffffu, r, o);
        if (lane == 0) sh[0] = r;
    }
    __syncthreads();
    return sh[0];
}

__device__ __forceinline__ float blockReduceMax(float v) {
    __shared__ float sh[32];
    int lane = threadIdx.x & 31, wid = threadIdx.x >> 5;
    #pragma unroll
    for (int o = 16; o > 0; o >>= 1) v = fmaxf(v, __shfl_xor_sync(0xffffffffu, v, o));
    __syncthreads();
    if (lane == 0) sh[wid] = v;
    __syncthreads();
    int nw = blockDim.x >> 5;
    float r = (threadIdx.x < nw) ? sh[threadIdx.x] : -3.4e38f;
    if (wid == 0) {
        #pragma unroll
        for (int o = 16; o > 0; o >>= 1) r = fmaxf(r, __shfl_xor_sync(0xffffffffu, r, o));
        if (lane == 0) sh[0] = r;
    }
    __syncthreads();
    return sh[0];
}

// ---------------- LayerNorm (+ optional AdaLN modulation or gamma/beta) ----------------
// sst != null : y = ln(x)*(1+scale)+shift with scale/shift = sst[i]+temb[b,i]
// else gamma != null : y = ln(x)*gamma+beta ; else plain
__global__ void __launch_bounds__(256) ln_kernel(
    const float* __restrict__ in, float* __restrict__ out,
    const float* __restrict__ gamma, const float* __restrict__ beta,
    const float* __restrict__ sst, const float* __restrict__ temb,
    int iShift, int iScale, int rowsPerB)
{
    long long r = blockIdx.x;
    const float* x = in + r * D;
    float s1 = 0.f, s2 = 0.f;
    for (int d = threadIdx.x; d < D; d += 256) { float v = x[d]; s1 += v; s2 += v * v; }
    s1 = blockReduceSum(s1);
    s2 = blockReduceSum(s2);
    float mean = s1 * (1.0f / D);
    float var  = s2 * (1.0f / D) - mean * mean;
    float rstd = rsqrtf(var + EPSV);
    int b = (int)(r / rowsPerB);
    for (int d = threadIdx.x; d < D; d += 256) {
        float y = (x[d] - mean) * rstd;
        if (sst) {
            float sc = sst[iScale * D + d] + temb[((long long)b * 6 + iScale) * D + d];
            float sh = sst[iShift * D + d] + temb[((long long)b * 6 + iShift) * D + d];
            y = y * (1.f + sc) + sh;
        } else if (gamma) {
            y = y * gamma[d] + beta[d];
        }
        out[r * D + d] = y;
    }
}

// ---------------- RMSNorm over D + optional RoPE, write [B,H,Srows,HD] ----------------
__global__ void __launch_bounds__(256) rms_heads_kernel(
    const float* __restrict__ in, int ldin, int off,
    const float* __restrict__ w, float* __restrict__ out, int Srows,
    const float* __restrict__ rcos, const float* __restrict__ rsin)
{
    long long r = blockIdx.x;         // 0 .. NB*Srows-1
    int b = (int)(r / Srows), s = (int)(r % Srows);
    const float* x = in + r * ldin + off;
    float s2 = 0.f;
    for (int d = threadIdx.x; d < D; d += 256) { float v = x[d]; s2 += v * v; }
    s2 = blockReduceSum(s2);
    float rms = rsqrtf(s2 * (1.0f / D) + EPSV);
    for (int d = threadIdx.x; d < D; d += 256) {
        int h = d >> 7, dd = d & 127;
        float v = x[d] * rms * w[d];
        if (rcos) {
            int pd = (dd < 64) ? d + 64 : d - 64;
            float vp = x[pd] * rms * w[pd];
            float c = rcos[s * HDIM + dd], sn = rsin[s * HDIM + dd];
            v = (dd < 64) ? (v * c - vp * sn) : (v * c + vp * sn);
        }
        out[(((long long)(b * NH + h)) * Srows + s) * HDIM + dd] = v;
    }
}

// ---------------- V transpose to [B,H,HD,Srows] ----------------
__global__ void __launch_bounds__(256) vtrans_kernel(
    const float* __restrict__ in, int ldin, int off,
    float* __restrict__ out, int Srows, long long total)
{
    for (long long i = blockIdx.x * 256LL + threadIdx.x; i < total; i += (long long)gridDim.x * 256) {
        long long r = i / D; int col = (int)(i % D);
        int h = col >> 7, d = col & 127;
        int b = (int)(r / Srows), s = (int)(r % Srows);
        out[(((long long)(b * NH + h)) * HDIM + d) * Srows + s] = in[r * ldin + off + col];
    }
}

// ---------------- row softmax (in place) ----------------
__global__ void __launch_bounds__(256) softmax_kernel(float* __restrict__ p, int len)
{
    long long r = blockIdx.x;
    float* x = p + r * (long long)len;
    float mx = -3.4e38f;
    for (int d = threadIdx.x; d < len; d += 256) mx = fmaxf(mx, x[d]);
    mx = blockReduceMax(mx);
    float sum = 0.f;
    for (int d = threadIdx.x; d < len; d += 256) { float e = __expf(x[d] - mx); x[d] = e; sum += e; }
    sum = blockReduceSum(sum);
    float inv = 1.0f / sum;
    for (int d = threadIdx.x; d < len; d += 256) x[d] *= inv;
}

// ---------------- generic batched NT GEMM: C = alpha*A*B^T (+bias)(+epilogue) ----------------
// A: [M,K] lda ; B: [N,K] ldb ; C: [M,N] ldc
// per-batch bases: (bi/innerN)*so + (bi%innerN)*si
// mode 0: plain ; 1: gelu(tanh) ; 2: res + gate*v (gate = sst[mi]+temb[b,mi]) ; 3: res + v
#define BM 128
#define BN 128
#define BKK 16
__global__ void __launch_bounds__(256) gemm_nt_kernel(
    const float* __restrict__ A, const float* __restrict__ B, float* __restrict__ C,
    int M, int N, int K, int lda, int ldb, int ldc,
    long long sAo, long long sAi, long long sBo, long long sBi,
    long long sCo, long long sCi, int innerN,
    const float* __restrict__ bias, float alpha, int mode,
    const float* __restrict__ res,
    const float* __restrict__ sst, const float* __restrict__ temb,
    int modIdx, int rowsPerB)
{
    int bi = blockIdx.z;
    long long aBase = (long long)(bi / innerN) * sAo + (long long)(bi % innerN) * sAi;
    long long bBase = (long long)(bi / innerN) * sBo + (long long)(bi % innerN) * sBi;
    long long cBase = (long long)(bi / innerN) * sCo + (long long)(bi % innerN) * sCi;
    int m0 = blockIdx.y * BM, n0 = blockIdx.x * BN;

    __shared__ float sA[BKK][BM + 4];
    __shared__ float sB[BKK][BN + 4];
    float acc[8][8];
    #pragma unroll
    for (int i = 0; i < 8; i++)
        #pragma unroll
        for (int j = 0; j < 8; j++) acc[i][j] = 0.f;

    int tid = threadIdx.x;
    const float* Ab = A + aBase + (long long)m0 * lda;
    const float* Bb = B + bBase + (long long)n0 * ldb;
    int r0 = (tid >> 4) * 8, c0 = (tid & 15) * 8;

    for (int k0 = 0; k0 < K; k0 += BKK) {
        #pragma unroll
        for (int i = 0; i < (BM * BKK) / 256; i++) {
            int idx = tid + i * 256;
            int m = idx >> 4, k = idx & 15;
            sA[k][m] = Ab[(long long)m * lda + k0 + k];
        }
        #pragma unroll
        for (int i = 0; i < (BN * BKK) / 256; i++) {
            int idx = tid + i * 256;
            int n = idx >> 4, k = idx & 15;
            sB[k][n] = Bb[(long long)n * ldb + k0 + k];
        }
        __syncthreads();
        #pragma unroll
        for (int kk = 0; kk < BKK; kk++) {
            float a[8], b[8];
            #pragma unroll
            for (int i = 0; i < 8; i++) a[i] = sA[kk][r0 + i];
            #pragma unroll
            for (int j = 0; j < 8; j++) b[j] = sB[kk][c0 + j];
            #pragma unroll
            for (int i = 0; i < 8; i++)
                #pragma unroll
                for (int j = 0; j < 8; j++) acc[i][j] = fmaf(a[i], b[j], acc[i][j]);
        }
        __syncthreads();
    }

    int gr0 = m0 + r0, gc0 = n0 + c0;
    #pragma unroll
    for (int i = 0; i < 8; i++) {
        long long r = gr0 + i;
        #pragma unroll
        for (int j = 0; j < 8; j++) {
            long long c = gc0 + j;
            float v = acc[i][j] * alpha;
            if (bias) v += bias[c];
            if (mode == 1) {
                float x = v;
                float t = tanhf(0.7978845608028654f * (x + 0.044715f * x * x * x));
                v = 0.5f * x * (1.f + t);
            }
            long long ci = cBase + r * ldc + c;
            if (mode == 2) {
                int b_ = (int)(r / rowsPerB);
                float g = sst[(long long)modIdx * D + c] +
                          temb[((long long)b_ * 6 + modIdx) * D + c];
                v = res[ci] + g * v;
            } else if (mode == 3) {
                v = res[ci] + v;
            }
            C[ci] = v;
        }
    }
}

// ---------------- host-side launch helper ----------------
static void gemm(const float* A, const float* B, float* C,
                 int M, int N, int K, int lda, int ldb, int ldc,
                 long long sAo, long long sAi, long long sBo, long long sBi,
                 long long sCo, long long sCi, int innerN, int nbatch,
                 const float* bias, float alpha, int mode,
                 const float* res, const float* sst, const float* temb,
                 int modIdx, int rowsPerB)
{
    dim3 grid(N / BN, M / BM, nbatch), block(256);
    gemm_nt_kernel<<<grid, block>>>(A, B, C, M, N, K, lda, ldb, ldc,
                                    sAo, sAi, sBo, sBi, sCo, sCi, innerN,
                                    bias, alpha, mode, res, sst, temb, modIdx, rowsPerB);
}

extern "C" void kernel_launch(void* const* d_in, const int* in_sizes, int n_in,
                              void* d_out, int out_size)
{
    const float* h    = (const float*)d_in[0];
    const float* enc  = (const float*)d_in[1];
    const float* temb = (const float*)d_in[2];
    const float* rcos = (const float*)d_in[3];
    const float* rsin = (const float*)d_in[4];
    const float* sst  = (const float*)d_in[5];
    const float* w_qkv = (const float*)d_in[6];
    const float* b_qkv = (const float*)d_in[7];
    const float* rms_q1 = (const float*)d_in[8];
    const float* rms_k1 = (const float*)d_in[9];
    const float* w_o1 = (const float*)d_in[10];
    const float* b_o1 = (const float*)d_in[11];
    const float* ln2_g = (const float*)d_in[12];
    const float* ln2_b = (const float*)d_in[13];
    const float* w_q2 = (const float*)d_in[14];
    const float* b_q2 = (const float*)d_in[15];
    const float* w_kv2 = (const float*)d_in[16];
    const float* b_kv2 = (const float*)d_in[17];
    const float* rms_q2 = (const float*)d_in[18];
    const float* rms_k2 = (const float*)d_in[19];
    const float* w_o2 = (const float*)d_in[20];
    const float* b_o2 = (const float*)d_in[21];
    const float* w_ff1 = (const float*)d_in[22];
    const float* b_ff1 = (const float*)d_in[23];
    const float* w_ff2 = (const float*)d_in[24];
    const float* b_ff2 = (const float*)d_in[25];
    float* out = (float*)d_out;

    float *px, *pqkv, *pq, *pk, *pvT, *pattn, *ph1, *ph2, *pkv2, *pmid, *plog;
    cudaGetSymbolAddress((void**)&px,    g_x);
    cudaGetSymbolAddress((void**)&pqkv,  g_qkv);
    cudaGetSymbolAddress((void**)&pq,    g_q);
    cudaGetSymbolAddress((void**)&pk,    g_k);
    cudaGetSymbolAddress((void**)&pvT,   g_vT);
    cudaGetSymbolAddress((void**)&pattn, g_attn);
    cudaGetSymbolAddress((void**)&ph1,   g_h1);
    cudaGetSymbolAddress((void**)&ph2,   g_h2);
    cudaGetSymbolAddress((void**)&pkv2,  g_kv2);
    cudaGetSymbolAddress((void**)&pmid,  g_mid);
    cudaGetSymbolAddress((void**)&plog,  g_logits);

    const float scale = 0.08838834764831845f;  // HD^-0.5
    const long long uQ = (long long)SSELF * HDIM;   // per-(b,h) stride q/k self
    const long long uL = (long long)SSELF * SSELF;  // logits self
    const long long uV = (long long)HDIM * SSELF;   // vT self
    const long long uK2 = (long long)SCROSS * HDIM;
    const long long uL2 = (long long)SSELF * SCROSS;
    const long long uV2 = (long long)HDIM * SCROSS;

    // 1) x = LN(h)*(1+scale_sa)+shift_sa
    ln_kernel<<<TOK, 256>>>(h, px, nullptr, nullptr, sst, temb, 0, 1, SSELF);
    // 2) qkv = x @ w_qkv^T + b_qkv
    gemm(px, w_qkv, pqkv, TOK, 3 * D, D, D, D, 3 * D, 0, 0, 0, 0, 0, 0, 1, 1,
         b_qkv, 1.f, 0, nullptr, nullptr, nullptr, 0, 0);
    // 3-5) rms+rope q,k ; v transpose
    rms_heads_kernel<<<TOK, 256>>>(pqkv, 3 * D, 0,     rms_q1, pq, SSELF, rcos, rsin);
    rms_heads_kernel<<<TOK, 256>>>(pqkv, 3 * D, D,     rms_k1, pk, SSELF, rcos, rsin);
    vtrans_kernel<<<2048, 256>>>(pqkv, 3 * D, 2 * D, pvT, SSELF, (long long)TOK * D);
    // 6) logits = scale * q @ k^T  (batched BH)
    gemm(pq, pk, plog, SSELF, SSELF, HDIM, HDIM, HDIM, SSELF,
         NH * uQ, uQ, NH * uQ, uQ, NH * uL, uL, NH, BH,
         nullptr, scale, 0, nullptr, nullptr, nullptr, 0, 0);
    // 7) softmax
    softmax_kernel<<<BH * SSELF, 256>>>(plog, SSELF);
    // 8) attn = P @ vT^T -> merged [TOK, D]
    gemm(plog, pvT, pattn, SSELF, HDIM, SSELF, SSELF, SSELF, D,
         NH * uL, uL, NH * uV, uV, (long long)SSELF * D, HDIM, NH, BH,
         nullptr, 1.f, 0, nullptr, nullptr, nullptr, 0, 0);
    // 9) h1 = h + gate_sa * (attn @ w_o1^T + b_o1)
    gemm(pattn, w_o1, ph1, TOK, D, D, D, D, D, 0, 0, 0, 0, 0, 0, 1, 1,
         b_o1, 1.f, 2, h, sst, temb, 2, SSELF);
    // 10) x2 = LN(h1, g, b)
    ln_kernel<<<TOK, 256>>>(ph1, px, ln2_g, ln2_b, nullptr, nullptr, 0, 0, SSELF);
    // 11) q2lin = x2 @ w_q2^T + b_q2
    gemm(px, w_q2, pqkv, TOK, D, D, D, D, D, 0, 0, 0, 0, 0, 0, 1, 1,
         b_q2, 1.f, 0, nullptr, nullptr, nullptr, 0, 0);
    // 12) q2 heads (rms, no rope)
    rms_heads_kernel<<<TOK, 256>>>(pqkv, D, 0, rms_q2, pq, SSELF, nullptr, nullptr);
    // 13) kv2 = enc @ w_kv2^T + b_kv2
    gemm(enc, w_kv2, pkv2, TOKC, 2 * D, D, D, D, 2 * D, 0, 0, 0, 0, 0, 0, 1, 1,
         b_kv2, 1.f, 0, nullptr, nullptr, nullptr, 0, 0);
    // 14-15) k2 heads (rms), v2 transpose
    rms_heads_kernel<<<TOKC, 256>>>(pkv2, 2 * D, 0, rms_k2, pk, SCROSS, nullptr, nullptr);
    vtrans_kernel<<<512, 256>>>(pkv2, 2 * D, D, pvT, SCROSS, (long long)TOKC * D);
    // 16) logits2 = scale * q2 @ k2^T
    gemm(pq, pk, plog, SSELF, SCROSS, HDIM, HDIM, HDIM, SCROSS,
         NH * uQ, uQ, NH * uK2, uK2, NH * uL2, uL2, NH, BH,
         nullptr, scale, 0, nullptr, nullptr, nullptr, 0, 0);
    // 17) softmax
    softmax_kernel<<<BH * SSELF, 256>>>(plog, SCROSS);
    // 18) attn2 = P2 @ v2T^T -> merged
    gemm(plog, pvT, pattn, SSELF, HDIM, SCROSS, SCROSS, SCROSS, D,
         NH * uL2, uL2, NH * uV2, uV2, (long long)SSELF * D, HDIM, NH, BH,
         nullptr, 1.f, 0, nullptr, nullptr, nullptr, 0, 0);
    // 19) h2 = h1 + attn2 @ w_o2^T + b_o2
    gemm(pattn, w_o2, ph2, TOK, D, D, D, D, D, 0, 0, 0, 0, 0, 0, 1, 1,
         b_o2, 1.f, 3, ph1, nullptr, nullptr, 0, SSELF);
    // 20) xff = LN(h2)*(1+scale_ff)+shift_ff
    ln_kernel<<<TOK, 256>>>(ph2, px, nullptr, nullptr, sst, temb, 3, 4, SSELF);
    // 21) mid = gelu(xff @ w_ff1^T + b_ff1)
    gemm(px, w_ff1, pmid, TOK, FFND, D, D, D, FFND, 0, 0, 0, 0, 0, 0, 1, 1,
         b_ff1, 1.f, 1, nullptr, nullptr, nullptr, 0, 0);
    // 22) out = h2 + gate_ff * (mid @ w_ff2^T + b_ff2)
    gemm(pmid, w_ff2, out, TOK, D, FFND, FFND, FFND, D, 0, 0, 0, 0, 0, 0, 1, 1,
         b_ff2, 1.f, 2, ph2, sst, temb, 5, SSELF);

    (void)in_sizes; (void)n_in; (void)out_size;
}

// round 3
// speedup vs baseline: 2.9683x; 2.9683x over previous
#include <cuda_runtime.h>
#include <cuda_bf16.h>
#include <cstdint>
#include <math.h>

// ---------------- problem constants ----------------
#define D      2560
#define SSELF  2048
#define SCROSS 512
#define NB     2
#define NH     20
#define HDIM   128
#define FFND   10240
#define TOK    4096
#define TOKC   1024
#define BH     40
#define EPSV   1e-6f

typedef __nv_bfloat16 bf16;

// ---------------- scratch (device globals) ----------------
__device__ float g_qkv [(size_t)TOK * 3 * D];
__device__ float g_kv2 [(size_t)TOKC * 2 * D];
__device__ float g_h1  [(size_t)TOK * D];
__device__ float g_h2  [(size_t)TOK * D];
__device__ float g_logits[(size_t)BH * SSELF * SSELF];

__device__ bf16 g_xh[(size_t)TOK * D],  g_xl[(size_t)TOK * D];
__device__ bf16 g_qh[(size_t)TOK * D],  g_ql[(size_t)TOK * D];
__device__ bf16 g_kh[(size_t)TOK * D],  g_kl[(size_t)TOK * D];
__device__ bf16 g_vh[(size_t)TOK * D],  g_vl[(size_t)TOK * D];
__device__ bf16 g_ah[(size_t)TOK * D],  g_al[(size_t)TOK * D];
__device__ bf16 g_mh[(size_t)TOK * FFND], g_ml[(size_t)TOK * FFND];
__device__ bf16 g_Ph[(size_t)BH * SSELF * SSELF], g_Pl[(size_t)BH * SSELF * SSELF];
__device__ bf16 g_ench[(size_t)TOKC * D], g_encl[(size_t)TOKC * D];

__device__ bf16 g_wqkvh[(size_t)3 * D * D], g_wqkvl[(size_t)3 * D * D];
__device__ bf16 g_wo1h [(size_t)D * D],     g_wo1l [(size_t)D * D];
__device__ bf16 g_wq2h [(size_t)D * D],     g_wq2l [(size_t)D * D];
__device__ bf16 g_wkv2h[(size_t)2 * D * D], g_wkv2l[(size_t)2 * D * D];
__device__ bf16 g_wo2h [(size_t)D * D],     g_wo2l [(size_t)D * D];
__device__ bf16 g_wff1h[(size_t)FFND * D],  g_wff1l[(size_t)FFND * D];
__device__ bf16 g_wff2h[(size_t)D * FFND],  g_wff2l[(size_t)D * FFND];

// ---------------- small helpers ----------------
__device__ __forceinline__ void split2(float v, bf16& h, bf16& l) {
    h = __float2bfloat16(v);
    l = __float2bfloat16(v - __bfloat162float(h));
}

__device__ __forceinline__ uint32_t smem_u32(const void* p) {
    uint32_t a;
    asm("{ .reg .u64 t; cvta.to.shared.u64 t, %1; cvt.u32.u64 %0, t; }" : "=r"(a) : "l"(p));
    return a;
}

#define CP_ASYNC16(dst, src) \
    asm volatile("cp.async.cg.shared.global [%0], [%1], 16;" :: "r"(dst), "l"(src))
#define CP_COMMIT() asm volatile("cp.async.commit_group;" ::: "memory")
#define CP_WAIT1()  asm volatile("cp.async.wait_group 1;" ::: "memory")

__device__ __forceinline__ void ldsm4(uint32_t* r, uint32_t addr) {
    asm volatile("ldmatrix.sync.aligned.m8n8.x4.shared.b16 {%0,%1,%2,%3}, [%4];"
        : "=r"(r[0]), "=r"(r[1]), "=r"(r[2]), "=r"(r[3]) : "r"(addr));
}

__device__ __forceinline__ void mma16816(float* c, const uint32_t* a, const uint32_t* b) {
    asm volatile("mma.sync.aligned.m16n8k16.row.col.f32.bf16.bf16.f32 "
        "{%0,%1,%2,%3}, {%4,%5,%6,%7}, {%8,%9}, {%0,%1,%2,%3};"
        : "+f"(c[0]), "+f"(c[1]), "+f"(c[2]), "+f"(c[3])
        : "r"(a[0]), "r"(a[1]), "r"(a[2]), "r"(a[3]), "r"(b[0]), "r"(b[1]));
}

// ---------------- reductions ----------------
__device__ __forceinline__ float blockReduceSum(float v) {
    __shared__ float sh[32];
    int lane = threadIdx.x & 31, wid = threadIdx.x >> 5;
    #pragma unroll
    for (int o = 16; o > 0; o >>= 1) v += __shfl_xor_sync(0xffffffffu, v, o);
    __syncthreads();
    if (lane == 0) sh[wid] = v;
    __syncthreads();
    int nw = blockDim.x >> 5;
    float r = (threadIdx.x < nw) ? sh[threadIdx.x] : 0.0f;
    if (wid == 0) {
        #pragma unroll
        for (int o = 16; o > 0; o >>= 1) r += __shfl_xor_sync(0xffffffffu, r, o);
        if (lane == 0) sh[0] = r;
    }
    __syncthreads();
    return sh[0];
}

__device__ __forceinline__ float blockReduceMax(float v) {
    __shared__ float sh[32];
    int lane = threadIdx.x & 31, wid = threadIdx.x >> 5;
    #pragma unroll
    for (int o = 16; o > 0; o >>= 1) v = fmaxf(v, __shfl_xor_sync(0xffffffffu, v, o));
    __syncthreads();
    if (lane == 0) sh[wid] = v;
    __syncthreads();
    int nw = blockDim.x >> 5;
    float r = (threadIdx.x < nw) ? sh[threadIdx.x] : -3.4e38f;
    if (wid == 0) {
        #pragma unroll
        for (int o = 16; o > 0; o >>= 1) r = fmaxf(r, __shfl_xor_sync(0xffffffffu, r, o));
        if (lane == 0) sh[0] = r;
    }
    __syncthreads();
    return sh[0];
}

// ---------------- elementwise producers (emit hi/lo bf16) ----------------
__global__ void __launch_bounds__(256) ln_kernel(
    const float* __restrict__ in, bf16* __restrict__ oh, bf16* __restrict__ ol,
    const float* __restrict__ gamma, const float* __restrict__ beta,
    const float* __restrict__ sst, const float* __restrict__ temb,
    int iShift, int iScale, int rowsPerB)
{
    long long r = blockIdx.x;
    const float* x = in + r * D;
    float s1 = 0.f, s2 = 0.f;
    for (int d = threadIdx.x; d < D; d += 256) { float v = x[d]; s1 += v; s2 += v * v; }
    s1 = blockReduceSum(s1);
    s2 = blockReduceSum(s2);
    float mean = s1 * (1.0f / D);
    float var  = s2 * (1.0f / D) - mean * mean;
    float rstd = rsqrtf(var + EPSV);
    int b = (int)(r / rowsPerB);
    for (int d = threadIdx.x; d < D; d += 256) {
        float y = (x[d] - mean) * rstd;
        if (sst) {
            float sc = sst[iScale * D + d] + temb[((long long)b * 6 + iScale) * D + d];
            float sh = sst[iShift * D + d] + temb[((long long)b * 6 + iShift) * D + d];
            y = y * (1.f + sc) + sh;
        } else if (gamma) {
            y = y * gamma[d] + beta[d];
        }
        bf16 h, l; split2(y, h, l);
        oh[r * D + d] = h; ol[r * D + d] = l;
    }
}

__global__ void __launch_bounds__(256) rms_heads_kernel(
    const float* __restrict__ in, int ldin, int off,
    const float* __restrict__ w, bf16* __restrict__ oh, bf16* __restrict__ ol, int Srows,
    const float* __restrict__ rcos, const float* __restrict__ rsin)
{
    long long r = blockIdx.x;
    int b = (int)(r / Srows), s = (int)(r % Srows);
    const float* x = in + r * ldin + off;
    float s2 = 0.f;
    for (int d = threadIdx.x; d < D; d += 256) { float v = x[d]; s2 += v * v; }
    s2 = blockReduceSum(s2);
    float rms = rsqrtf(s2 * (1.0f / D) + EPSV);
    for (int d = threadIdx.x; d < D; d += 256) {
        int h = d >> 7, dd = d & 127;
        float v = x[d] * rms * w[d];
        if (rcos) {
            int pd = (dd < 64) ? d + 64 : d - 64;
            float vp = x[pd] * rms * w[pd];
            float c = rcos[s * HDIM + dd], sn = rsin[s * HDIM + dd];
            v = (dd < 64) ? (v * c - vp * sn) : (v * c + vp * sn);
        }
        long long oi = (((long long)(b * NH + h)) * Srows + s) * HDIM + dd;
        bf16 hh, ll; split2(v, hh, ll);
        oh[oi] = hh; ol[oi] = ll;
    }
}

__global__ void __launch_bounds__(256) vtrans_kernel(
    const float* __restrict__ in, int ldin, int off,
    bf16* __restrict__ oh, bf16* __restrict__ ol, int Srows, long long total)
{
    for (long long i = blockIdx.x * 256LL + threadIdx.x; i < total; i += (long long)gridDim.x * 256) {
        long long r = i / D; int col = (int)(i % D);
        int h = col >> 7, d = col & 127;
        int b = (int)(r / Srows), s = (int)(r % Srows);
        long long oi = (((long long)(b * NH + h)) * HDIM + d) * Srows + s;
        bf16 hh, ll; split2(in[r * ldin + off + col], hh, ll);
        oh[oi] = hh; ol[oi] = ll;
    }
}

__global__ void __launch_bounds__(256) softmax_kernel(
    float* __restrict__ p, bf16* __restrict__ oh, bf16* __restrict__ ol, int len)
{
    long long r = blockIdx.x;
    float* x = p + r * (long long)len;
    float mx = -3.4e38f;
    for (int d = threadIdx.x; d < len; d += 256) mx = fmaxf(mx, x[d]);
    mx = blockReduceMax(mx);
    float sum = 0.f;
    for (int d = threadIdx.x; d < len; d += 256) { float e = __expf(x[d] - mx); x[d] = e; sum += e; }
    sum = blockReduceSum(sum);
    float inv = 1.0f / sum;
    for (int d = threadIdx.x; d < len; d += 256) {
        float v = x[d] * inv;
        bf16 hh, ll; split2(v, hh, ll);
        oh[r * (long long)len + d] = hh; ol[r * (long long)len + d] = ll;
    }
}

__global__ void __launch_bounds__(256) split_kernel(
    const float* __restrict__ in, bf16* __restrict__ oh, bf16* __restrict__ ol, long long n)
{
    for (long long i = blockIdx.x * 256LL + threadIdx.x; i < n; i += (long long)gridDim.x * 256) {
        bf16 h, l; split2(in[i], h, l);
        oh[i] = h; ol[i] = l;
    }
}

// ---------------- mma.sync split-bf16 GEMM ----------------
// C[m,n] = alpha * sum_k A[m,k]*B[n,k]  (+bias +epilogue)
// effective A = Ah+Al, B = Bh+Bl; compute Ah*Bh + Ah*Bl + Al*Bh
// BM=BN=128, BK=32, 3-stage cp.async pipeline, 8 warps (2x4 -> 64x32 per warp)
#define STAGE_BYTES 32768
#define OFF_AH 0
#define OFF_AL 8192
#define OFF_BH 16384
#define OFF_BL 24576
#define GEMM_SMEM (3 * STAGE_BYTES)

// swizzled byte offset within a 128x32 bf16 tile (row stride 64B, 4 16B chunks)
__device__ __forceinline__ uint32_t tswz(int row, int chunk) {
    return (uint32_t)(row * 64 + ((chunk ^ (row & 3)) << 4));
}

__global__ void __launch_bounds__(256, 1) gemm_tc_kernel(
    const bf16* __restrict__ Ah, const bf16* __restrict__ Al,
    const bf16* __restrict__ Bh, const bf16* __restrict__ Bl,
    float* __restrict__ C, bf16* __restrict__ Ch, bf16* __restrict__ Cl,
    int K, int lda, int ldb, int ldc,
    long long sAo, long long sAi, long long sBo, long long sBi,
    long long sCo, long long sCi, int innerN,
    const float* __restrict__ bias, float alpha, int mode,
    const float* __restrict__ res,
    const float* __restrict__ sst, const float* __restrict__ temb,
    int modIdx, int rowsPerB)
{
    extern __shared__ char smem[];
    uint32_t sbase = smem_u32(smem);
    int tid = threadIdx.x, wid = tid >> 5, lane = tid & 31;

    int bi = blockIdx.z;
    long long aBase = (long long)(bi / innerN) * sAo + (long long)(bi % innerN) * sAi;
    long long bBase = (long long)(bi / innerN) * sBo + (long long)(bi % innerN) * sBi;
    long long cBase = (long long)(bi / innerN) * sCo + (long long)(bi % innerN) * sCi;
    int m0 = blockIdx.y * 128, n0 = blockIdx.x * 128;

    const bf16* Ahp = Ah + aBase + (long long)m0 * lda;
    const bf16* Alp = Al + aBase + (long long)m0 * lda;
    const bf16* Bhp = Bh + bBase + (long long)n0 * ldb;
    const bf16* Blp = Bl + bBase + (long long)n0 * ldb;

    // loader: 2048 16B-chunks per stage, 8 per thread
    int lrow = tid >> 2;          // 0..63 base row within 512-chunk subtile section
    int lch  = tid & 3;
    int NC = K >> 5;

    auto load_stage = [&](int c) {
        int s = c - (c / 3) * 3;
        uint32_t st = sbase + s * STAGE_BYTES;
        int k0 = c << 5;
        #pragma unroll
        for (int half = 0; half < 2; half++) {
            int row = lrow + half * 64;
            uint32_t sw = tswz(row, lch);
            long long gk = k0 + lch * 8;
            CP_ASYNC16(st + OFF_AH + sw, Ahp + (long long)row * lda + gk);
            CP_ASYNC16(st + OFF_AL + sw, Alp + (long long)row * lda + gk);
            CP_ASYNC16(st + OFF_BH + sw, Bhp + (long long)row * ldb + gk);
            CP_ASYNC16(st + OFF_BL + sw, Blp + (long long)row * ldb + gk);
        }
    };

    float acc[4][4][4];
    #pragma unroll
    for (int i = 0; i < 4; i++)
        #pragma unroll
        for (int j = 0; j < 4; j++)
            #pragma unroll
            for (int e = 0; e < 4; e++) acc[i][j][e] = 0.f;

    int wm = (wid >> 2) * 64;   // warp m offset (0/64)
    int wn = (wid & 3) * 32;    // warp n offset

    load_stage(0); CP_COMMIT();
    if (NC > 1) load_stage(1);
    CP_COMMIT();

    for (int c = 0; c < NC; c++) {
        int s = c - (c / 3) * 3;
        CP_WAIT1();
        __syncthreads();
        if (c + 2 < NC) load_stage(c + 2);
        CP_COMMIT();

        uint32_t st = sbase + s * STAGE_BYTES;
        #pragma unroll
        for (int kk = 0; kk < 2; kk++) {
            uint32_t ah[4][4], al[4][4], bh[4][2], bl[4][2];
            // A fragments
            int rA = lane & 15, cA = (kk << 1) + (lane >> 4);
            #pragma unroll
            for (int mt = 0; mt < 4; mt++) {
                int r = wm + mt * 16 + rA;
                uint32_t off = tswz(r, cA);
                ldsm4(ah[mt], st + OFF_AH + off);
                ldsm4(al[mt], st + OFF_AL + off);
            }
            // B fragments (x4 covers two n8 tiles)
            int rB = (lane & 7) + ((lane >> 4) << 3);
            int cB = (kk << 1) + ((lane >> 3) & 1);
            #pragma unroll
            for (int ntp = 0; ntp < 2; ntp++) {
                int r = wn + ntp * 16 + rB;
                uint32_t off = tswz(r, cB);
                uint32_t t[4];
                ldsm4(t, st + OFF_BH + off);
                bh[2*ntp][0]=t[0]; bh[2*ntp][1]=t[1]; bh[2*ntp+1][0]=t[2]; bh[2*ntp+1][1]=t[3];
                ldsm4(t, st + OFF_BL + off);
                bl[2*ntp][0]=t[0]; bl[2*ntp][1]=t[1]; bl[2*ntp+1][0]=t[2]; bl[2*ntp+1][1]=t[3];
            }
            #pragma unroll
            for (int mt = 0; mt < 4; mt++)
                #pragma unroll
                for (int nt = 0; nt < 4; nt++) {
                    mma16816(acc[mt][nt], ah[mt], bh[nt]);
                    mma16816(acc[mt][nt], ah[mt], bl[nt]);
                    mma16816(acc[mt][nt], al[mt], bh[nt]);
                }
        }
        __syncthreads();
    }

    // ---- epilogue (direct from registers) ----
    int qrow = lane >> 2, qcol = (lane & 3) * 2;
    #pragma unroll
    for (int mt = 0; mt < 4; mt++) {
        #pragma unroll
        for (int nt = 0; nt < 4; nt++) {
            #pragma unroll
            for (int e = 0; e < 4; e++) {
                long long rrow = m0 + wm + mt * 16 + qrow + ((e >> 1) ? 8 : 0);
                int col = n0 + wn + nt * 8 + qcol + (e & 1);
                float v = acc[mt][nt][e] * alpha;
                if (bias) v += bias[col];
                if (mode == 1) {
                    float x = v;
                    float t = tanhf(0.7978845608028654f * (x + 0.044715f * x * x * x));
                    v = 0.5f * x * (1.f + t);
                }
                long long ci = cBase + rrow * ldc + col;
                if (mode == 2) {
                    int b_ = (int)(rrow / rowsPerB);
                    float g = sst[(long long)modIdx * D + col] +
                              temb[((long long)b_ * 6 + modIdx) * D + col];
                    v = res[ci] + g * v;
                } else if (mode == 3) {
                    v = res[ci] + v;
                }
                if (C) C[ci] = v;
                if (Ch) {
                    bf16 hh, ll; split2(v, hh, ll);
                    Ch[ci] = hh; Cl[ci] = ll;
                }
            }
        }
    }
}

// ---------------- host launch helper ----------------
static void gemm(const bf16* Ah, const bf16* Al, const bf16* Bh, const bf16* Bl,
                 float* C, bf16* Ch, bf16* Cl,
                 int M, int N, int K, int lda, int ldb, int ldc,
                 long long sAo, long long sAi, long long sBo, long long sBi,
                 long long sCo, long long sCi, int innerN, int nbatch,
                 const float* bias, float alpha, int mode,
                 const float* res, const float* sst, const float* temb,
                 int modIdx, int rowsPerB)
{
    dim3 grid(N / 128, M / 128, nbatch), block(256);
    gemm_tc_kernel<<<grid, block, GEMM_SMEM>>>(
        Ah, Al, Bh, Bl, C, Ch, Cl, K, lda, ldb, ldc,
        sAo, sAi, sBo, sBi, sCo, sCi, innerN,
        bias, alpha, mode, res, sst, temb, modIdx, rowsPerB);
}

#define GETP(sym) ({ void* _p; cudaGetSymbolAddress(&_p, sym); _p; })

extern "C" void kernel_launch(void* const* d_in, const int* in_sizes, int n_in,
                              void* d_out, int out_size)
{
    const float* h    = (const float*)d_in[0];
    const float* enc  = (const float*)d_in[1];
    const float* temb = (const float*)d_in[2];
    const float* rcos = (const float*)d_in[3];
    const float* rsin = (const float*)d_in[4];
    const float* sst  = (const float*)d_in[5];
    const float* w_qkv = (const float*)d_in[6];
    const float* b_qkv = (const float*)d_in[7];
    const float* rms_q1 = (const float*)d_in[8];
    const float* rms_k1 = (const float*)d_in[9];
    const float* w_o1 = (const float*)d_in[10];
    const float* b_o1 = (const float*)d_in[11];
    const float* ln2_g = (const float*)d_in[12];
    const float* ln2_b = (const float*)d_in[13];
    const float* w_q2 = (const float*)d_in[14];
    const float* b_q2 = (const float*)d_in[15];
    const float* w_kv2 = (const float*)d_in[16];
    const float* b_kv2 = (const float*)d_in[17];
    const float* rms_q2 = (const float*)d_in[18];
    const float* rms_k2 = (const float*)d_in[19];
    const float* w_o2 = (const float*)d_in[20];
    const float* b_o2 = (const float*)d_in[21];
    const float* w_ff1 = (const float*)d_in[22];
    const float* b_ff1 = (const float*)d_in[23];
    const float* w_ff2 = (const float*)d_in[24];
    const float* b_ff2 = (const float*)d_in[25];
    float* out = (float*)d_out;

    cudaFuncSetAttribute(gemm_tc_kernel, cudaFuncAttributeMaxDynamicSharedMemorySize, GEMM_SMEM);

    float* pqkv = (float*)GETP(g_qkv);
    float* pkv2 = (float*)GETP(g_kv2);
    float* ph1  = (float*)GETP(g_h1);
    float* ph2  = (float*)GETP(g_h2);
    float* plog = (float*)GETP(g_logits);
    bf16 *xh=(bf16*)GETP(g_xh), *xl=(bf16*)GETP(g_xl);
    bf16 *qh=(bf16*)GETP(g_qh), *ql=(bf16*)GETP(g_ql);
    bf16 *kh=(bf16*)GETP(g_kh), *kl=(bf16*)GETP(g_kl);
    bf16 *vh=(bf16*)GETP(g_vh), *vl=(bf16*)GETP(g_vl);
    bf16 *ath=(bf16*)GETP(g_ah), *atl=(bf16*)GETP(g_al);
    bf16 *mh=(bf16*)GETP(g_mh), *ml=(bf16*)GETP(g_ml);
    bf16 *Ph=(bf16*)GETP(g_Ph), *Pl=(bf16*)GETP(g_Pl);
    bf16 *ench=(bf16*)GETP(g_ench), *encl=(bf16*)GETP(g_encl);
    bf16 *wqkvh=(bf16*)GETP(g_wqkvh), *wqkvl=(bf16*)GETP(g_wqkvl);
    bf16 *wo1h=(bf16*)GETP(g_wo1h), *wo1l=(bf16*)GETP(g_wo1l);
    bf16 *wq2h=(bf16*)GETP(g_wq2h), *wq2l=(bf16*)GETP(g_wq2l);
    bf16 *wkv2h=(bf16*)GETP(g_wkv2h), *wkv2l=(bf16*)GETP(g_wkv2l);
    bf16 *wo2h=(bf16*)GETP(g_wo2h), *wo2l=(bf16*)GETP(g_wo2l);
    bf16 *wff1h=(bf16*)GETP(g_wff1h), *wff1l=(bf16*)GETP(g_wff1l);
    bf16 *wff2h=(bf16*)GETP(g_wff2h), *wff2l=(bf16*)GETP(g_wff2l);

    const float scale = 0.08838834764831845f;
    const long long uQ  = (long long)SSELF * HDIM;
    const long long uL  = (long long)SSELF * SSELF;
    const long long uV  = (long long)HDIM * SSELF;
    const long long uK2 = (long long)SCROSS * HDIM;
    const long long uL2 = (long long)SSELF * SCROSS;
    const long long uV2 = (long long)HDIM * SCROSS;

    // weight / encoder splits
    split_kernel<<<2048, 256>>>(w_qkv, wqkvh, wqkvl, (long long)3 * D * D);
    split_kernel<<<2048, 256>>>(w_o1,  wo1h,  wo1l,  (long long)D * D);
    split_kernel<<<2048, 256>>>(w_q2,  wq2h,  wq2l,  (long long)D * D);
    split_kernel<<<2048, 256>>>(w_kv2, wkv2h, wkv2l, (long long)2 * D * D);
    split_kernel<<<2048, 256>>>(w_o2,  wo2h,  wo2l,  (long long)D * D);
    split_kernel<<<2048, 256>>>(w_ff1, wff1h, wff1l, (long long)FFND * D);
    split_kernel<<<2048, 256>>>(w_ff2, wff2h, wff2l, (long long)D * FFND);
    split_kernel<<<2048, 256>>>(enc,   ench,  encl,  (long long)TOKC * D);

    // 1) x = LN(h)*(1+scale_sa)+shift_sa
    ln_kernel<<<TOK, 256>>>(h, xh, xl, nullptr, nullptr, sst, temb, 0, 1, SSELF);
    // 2) qkv
    gemm(xh, xl, wqkvh, wqkvl, pqkv, nullptr, nullptr, TOK, 3 * D, D, D, D, 3 * D,
         0,0,0,0,0,0,1,1, b_qkv, 1.f, 0, nullptr, nullptr, nullptr, 0, 0);
    // 3-5) heads
    rms_heads_kernel<<<TOK, 256>>>(pqkv, 3 * D, 0, rms_q1, qh, ql, SSELF, rcos, rsin);
    rms_heads_kernel<<<TOK, 256>>>(pqkv, 3 * D, D, rms_k1, kh, kl, SSELF, rcos, rsin);
    vtrans_kernel<<<2048, 256>>>(pqkv, 3 * D, 2 * D, vh, vl, SSELF, (long long)TOK * D);
    // 6) logits = scale * q k^T
    gemm(qh, ql, kh, kl, plog, nullptr, nullptr, SSELF, SSELF, HDIM, HDIM, HDIM, SSELF,
         NH * uQ, uQ, NH * uQ, uQ, NH * uL, uL, NH, BH,
         nullptr, scale, 0, nullptr, nullptr, nullptr, 0, 0);
    // 7) softmax
    softmax_kernel<<<BH * SSELF, 256>>>(plog, Ph, Pl, SSELF);
    // 8) attn = P @ vT^T
    gemm(Ph, Pl, vh, vl, nullptr, ath, atl, SSELF, HDIM, SSELF, SSELF, SSELF, D,
         NH * uL, uL, NH * uV, uV, (long long)SSELF * D, HDIM, NH, BH,
         nullptr, 1.f, 0, nullptr, nullptr, nullptr, 0, 0);
    // 9) h1 = h + gate_sa * (attn W_o1^T + b)
    gemm(ath, atl, wo1h, wo1l, ph1, nullptr, nullptr, TOK, D, D, D, D, D,
         0,0,0,0,0,0,1,1, b_o1, 1.f, 2, h, sst, temb, 2, SSELF);
    // 10) x2 = LN(h1)
    ln_kernel<<<TOK, 256>>>(ph1, xh, xl, ln2_g, ln2_b, nullptr, nullptr, 0, 0, SSELF);
    // 11) q2lin
    gemm(xh, xl, wq2h, wq2l, pqkv, nullptr, nullptr, TOK, D, D, D, D, D,
         0,0,0,0,0,0,1,1, b_q2, 1.f, 0, nullptr, nullptr, nullptr, 0, 0);
    // 12) q2 heads
    rms_heads_kernel<<<TOK, 256>>>(pqkv, D, 0, rms_q2, qh, ql, SSELF, nullptr, nullptr);
    // 13) kv2
    gemm(ench, encl, wkv2h, wkv2l, pkv2, nullptr, nullptr, TOKC, 2 * D, D, D, D, 2 * D,
         0,0,0,0,0,0,1,1, b_kv2, 1.f, 0, nullptr, nullptr, nullptr, 0, 0);
    // 14-15) k2, v2
    rms_heads_kernel<<<TOKC, 256>>>(pkv2, 2 * D, 0, rms_k2, kh, kl, SCROSS, nullptr, nullptr);
    vtrans_kernel<<<512, 256>>>(pkv2, 2 * D, D, vh, vl, SCROSS, (long long)TOKC * D);
    // 16) logits2
    gemm(qh, ql, kh, kl, plog, nullptr, nullptr, SSELF, SCROSS, HDIM, HDIM, HDIM, SCROSS,
         NH * uQ, uQ, NH * uK2, uK2, NH * uL2, uL2, NH, BH,
         nullptr, scale, 0, nullptr, nullptr, nullptr, 0, 0);
    // 17) softmax2
    softmax_kernel<<<BH * SSELF, 256>>>(plog, Ph, Pl, SCROSS);
    // 18) attn2
    gemm(Ph, Pl, vh, vl, nullptr, ath, atl, SSELF, HDIM, SCROSS, SCROSS, SCROSS, D,
         NH * uL2, uL2, NH * uV2, uV2, (long long)SSELF * D, HDIM, NH, BH,
         nullptr, 1.f, 0, nullptr, nullptr, nullptr, 0, 0);
    // 19) h2 = h1 + attn2 W_o2^T + b
    gemm(ath, atl, wo2h, wo2l, ph2, nullptr, nullptr, TOK, D, D, D, D, D,
         0,0,0,0,0,0,1,1, b_o2, 1.f, 3, ph1, nullptr, nullptr, 0, SSELF);
    // 20) xff
    ln_kernel<<<TOK, 256>>>(ph2, xh, xl, nullptr, nullptr, sst, temb, 3, 4, SSELF);
    // 21) mid = gelu(xff W_ff1^T + b)
    gemm(xh, xl, wff1h, wff1l, nullptr, mh, ml, TOK, FFND, D, D, D, FFND,
         0,0,0,0,0,0,1,1, b_ff1, 1.f, 1, nullptr, nullptr, nullptr, 0, 0);
    // 22) out = h2 + gate_ff * (mid W_ff2^T + b)
    gemm(mh, ml, wff2h, wff2l, out, nullptr, nullptr, TOK, D, FFND, FFND, FFND, D,
         0,0,0,0,0,0,1,1, b_ff2, 1.f, 2, ph2, sst, temb, 5, SSELF);

    (void)in_sizes; (void)n_in; (void)out_size;
}